// round 15
// baseline (speedup 1.0000x reference)
#include <cuda_runtime.h>

#define EMBED     128
#define MAXN      200
#define NTHREADS  256
#define LN_EPS    1e-5f

// Interleaved pre-transposed weights: g_Wp[e*128+d] = (W_tail[d][e], W_head[d][e])
__device__ float2 g_Wp[EMBED * EMBED];

__global__ void transpose_w(const float* __restrict__ Wt, const float* __restrict__ Wh) {
    int i = blockIdx.x * blockDim.x + threadIdx.x;
    if (i < EMBED * EMBED) {
        int d = i >> 7;
        int e = i & 127;
        g_Wp[e * EMBED + d] = make_float2(Wt[i], Wh[i]);
    }
}

// One CTA = one batch element, BOTH sides. Score+exp+aggregate fused, 4 rows/iter.
// Gathers use __ldcs (streaming) so the 192KB weight working set stays L1-resident.
// 3 CTAs/SM: ~85 regs lets ptxas software-pipeline two iterations' load batches.
__global__ __launch_bounds__(NTHREADS, 3)
void encoder_kernel(const int*   __restrict__ entity,
                    const int*   __restrict__ conn_left,
                    const int*   __restrict__ conn_right,
                    const float* __restrict__ emb,
                    const float* __restrict__ W_bil,
                    const float* __restrict__ gamma,
                    const float* __restrict__ beta,
                    float*       __restrict__ out,
                    int batch, int pad_idx)
{
    const int b    = blockIdx.x;
    const int tid  = threadIdx.x;
    const int lane = tid & 31;
    const int wid  = tid >> 5;

    __shared__ float s_weak[EMBED];
    __shared__ float s_head[2][EMBED];
    __shared__ float s_qp[2 * EMBED];
    __shared__ __align__(16) unsigned s_roff[2][MAXN];   // rel row byte-offsets
    __shared__ __align__(16) unsigned s_toff[2][MAXN];   // tail row byte-offsets
    __shared__ float s_aggp[8][EMBED];
    __shared__ float s_agg[2][EMBED];
    __shared__ float s_part[2][2][EMBED];
    __shared__ float s_red[8];
    __shared__ float s_red2[8];

    // ---- Stage 0: heads, weak_rel, neighbor offsets for both sides ----
    if (tid < EMBED) {
        int e0 = entity[2 * b];
        int e1 = entity[2 * b + 1];
        float hl = __ldcs(&emb[(size_t)e0 * EMBED + tid]);
        float hr = __ldcs(&emb[(size_t)e1 * EMBED + tid]);
        s_weak[tid]    = hr - hl;
        s_head[0][tid] = hl;
        s_head[1][tid] = hr;
    }
    for (int i = tid; i < 2 * MAXN; i += NTHREADS) {
        int s = (i < MAXN) ? 0 : 1;
        int m = (i < MAXN) ? i : i - MAXN;
        const int* conn = (s == 0 ? conn_left : conn_right) + (long)b * MAXN * 2;
        int2 c = reinterpret_cast<const int2*>(conn)[m];
        s_roff[s][m] = (unsigned)c.x << 9;     // row * 512 bytes
        s_toff[s][m] = (unsigned)c.y << 9;
    }
    __syncthreads();

    // ---- Stage 1: q = weak_rel @ W_bil (shared by both sides), split-K ----
    {
        int half = tid >> 7;
        int e    = tid & 127;
        int d0   = half * 64;
        float acc = 0.f;
        #pragma unroll 8
        for (int d = d0; d < d0 + 64; d++)
            acc = fmaf(s_weak[d], W_bil[d * EMBED + e], acc);
        s_qp[half * EMBED + e] = acc;
    }
    __syncthreads();

    // ---- Stage 2 (FUSED): score -> exp -> aggregate, 4 rows per iteration ----
    {
        float4 q0 = reinterpret_cast<const float4*>(s_qp)[lane];
        float4 q1 = reinterpret_cast<const float4*>(s_qp + EMBED)[lane];
        float4 qv = make_float4(q0.x + q1.x, q0.y + q1.y, q0.z + q1.z, q0.w + q1.w);

        const char* embB = reinterpret_cast<const char*>(emb) + (unsigned)(lane << 4);
        const unsigned pad_off = (unsigned)pad_idx << 9;

        const int s    = wid >> 2;
        const int w4   = wid & 3;
        const bool hi16 = (lane & 16) != 0;
        const bool hi8  = (lane & 8)  != 0;

        float  lsum = 0.f;
        float4 a01 = make_float4(0.f, 0.f, 0.f, 0.f);
        float4 a23 = make_float4(0.f, 0.f, 0.f, 0.f);

        // 4-row fused body; m is a multiple of 4 (int4-aligned offset loads)
        auto body4 = [&](int m) {
            int4 ro = *reinterpret_cast<const int4*>(&s_roff[s][m]);
            int4 to = *reinterpret_cast<const int4*>(&s_toff[s][m]);
            // lane groups after reduce: [0-7]=row0, [8-15]=row2, [16-23]=row1, [24-31]=row3
            unsigned gA = hi8  ? (unsigned)ro.z : (unsigned)ro.x;
            unsigned gB = hi8  ? (unsigned)ro.w : (unsigned)ro.y;
            unsigned my_off = hi16 ? gB : gA;

            float4 v0 = __ldcs(reinterpret_cast<const float4*>(embB + (unsigned)ro.x));
            float4 v1 = __ldcs(reinterpret_cast<const float4*>(embB + (unsigned)ro.y));
            float4 v2 = __ldcs(reinterpret_cast<const float4*>(embB + (unsigned)ro.z));
            float4 v3 = __ldcs(reinterpret_cast<const float4*>(embB + (unsigned)ro.w));
            float4 u0 = __ldcs(reinterpret_cast<const float4*>(embB + (unsigned)to.x));
            float4 u1 = __ldcs(reinterpret_cast<const float4*>(embB + (unsigned)to.y));
            float4 u2 = __ldcs(reinterpret_cast<const float4*>(embB + (unsigned)to.z));
            float4 u3 = __ldcs(reinterpret_cast<const float4*>(embB + (unsigned)to.w));

            float p0 = v0.x*qv.x + v0.y*qv.y + v0.z*qv.z + v0.w*qv.w;
            float p1 = v1.x*qv.x + v1.y*qv.y + v1.z*qv.z + v1.w*qv.w;
            float p2 = v2.x*qv.x + v2.y*qv.y + v2.z*qv.z + v2.w*qv.w;
            float p3 = v3.x*qv.x + v3.y*qv.y + v3.z*qv.z + v3.w*qv.w;

            // 4-row reduce in 5 shfls
            float x01 = hi16 ? p1 : p0;
            float y01 = hi16 ? p0 : p1;
            x01 += __shfl_xor_sync(0xffffffffu, y01, 16);
            float x23 = hi16 ? p3 : p2;
            float y23 = hi16 ? p2 : p3;
            x23 += __shfl_xor_sync(0xffffffffu, y23, 16);
            float x = hi8 ? x23 : x01;
            float y = hi8 ? x01 : x23;
            x += __shfl_xor_sync(0xffffffffu, y, 8);
            x += __shfl_xor_sync(0xffffffffu, x, 4);
            x += __shfl_xor_sync(0xffffffffu, x, 2);
            x += __shfl_xor_sync(0xffffffffu, x, 1);

            float e = (my_off == pad_off) ? 0.f : __expf(x);

            float att0 = __shfl_sync(0xffffffffu, e, 0);
            float att2 = __shfl_sync(0xffffffffu, e, 8);
            float att1 = __shfl_sync(0xffffffffu, e, 16);
            float att3 = __shfl_sync(0xffffffffu, e, 24);
            lsum += (att0 + att1) + (att2 + att3);

            a01.x = fmaf(att0, u0.x, fmaf(att1, u1.x, a01.x));
            a01.y = fmaf(att0, u0.y, fmaf(att1, u1.y, a01.y));
            a01.z = fmaf(att0, u0.z, fmaf(att1, u1.z, a01.z));
            a01.w = fmaf(att0, u0.w, fmaf(att1, u1.w, a01.w));
            a23.x = fmaf(att2, u2.x, fmaf(att3, u3.x, a23.x));
            a23.y = fmaf(att2, u2.y, fmaf(att3, u3.y, a23.y));
            a23.z = fmaf(att2, u2.z, fmaf(att3, u3.z, a23.z));
            a23.w = fmaf(att2, u2.w, fmaf(att3, u3.w, a23.w));
        };

        // rows 0..191: warp w4 handles m = w4*4 + it*16 (fully unrolled so
        // ptxas can software-pipeline load batches across iterations)
        #pragma unroll
        for (int it = 0; it < 12; it++)
            body4(w4 * 4 + it * 16);
        // rows 192..199: warps w4==0,1 take one more 4-row group
        if (w4 < 2)
            body4(192 + w4 * 4);

        float4 at = make_float4(a01.x + a23.x, a01.y + a23.y,
                                a01.z + a23.z, a01.w + a23.w);
        reinterpret_cast<float4*>(s_aggp[wid])[lane] = at;
        if (lane == 0) s_red[wid] = lsum;
    }
    __syncthreads();

    // ---- Stage 3: reduce warp partials per side, normalize ----
    {
        int s = tid >> 7;
        int d = tid & 127;
        float tot = s_red[s * 4] + s_red[s * 4 + 1] + s_red[s * 4 + 2] + s_red[s * 4 + 3];
        float inv_sum = 1.f / tot;
        float a = s_aggp[s * 4][d] + s_aggp[s * 4 + 1][d]
                + s_aggp[s * 4 + 2][d] + s_aggp[s * 4 + 3][d];
        s_agg[s][d] = a * inv_sum;
    }
    __syncthreads();

    // ---- Stage 4: both matvecs share interleaved W loads (LDG.64, L1-cached) ----
    {
        int half = tid >> 7;
        int d    = tid & 127;
        int e0   = half * 64;
        float accL = 0.f, accR = 0.f;
        #pragma unroll 4
        for (int e = e0; e < e0 + 64; e++) {
            float2 w = g_Wp[e * EMBED + d];        // (wt, wh)
            accL = fmaf(s_agg[0][e],  w.x, accL);
            accL = fmaf(s_head[0][e], w.y, accL);
            accR = fmaf(s_agg[1][e],  w.x, accR);
            accR = fmaf(s_head[1][e], w.y, accR);
        }
        s_part[half][0][d] = accL;
        s_part[half][1][d] = accR;
    }
    __syncthreads();

    // ---- Stage 5: residual + LayerNorm per side ----
    {
        int s = tid >> 7;
        int d = tid & 127;
        float h = fmaxf(s_part[0][s][d] + s_part[1][s][d], 0.f);
        float x = h + s_head[s][d];

        float sx = x, sxx = x * x;
        #pragma unroll
        for (int o = 16; o; o >>= 1) {
            sx  += __shfl_xor_sync(0xffffffffu, sx,  o);
            sxx += __shfl_xor_sync(0xffffffffu, sxx, o);
        }
        if (lane == 0) { s_red[wid] = sx; s_red2[wid] = sxx; }
        __syncthreads();
        float tsum = s_red[s * 4]  + s_red[s * 4 + 1]  + s_red[s * 4 + 2]  + s_red[s * 4 + 3];
        float tsq  = s_red2[s * 4] + s_red2[s * 4 + 1] + s_red2[s * 4 + 2] + s_red2[s * 4 + 3];
        float mu      = tsum * (1.f / EMBED);
        float var     = tsq  * (1.f / EMBED) - mu * mu;
        float inv_std = rsqrtf(var + LN_EPS);
        float o = (x - mu) * inv_std * gamma[d] + beta[d];
        out[((long)s * batch + b) * EMBED + d] = o;
    }
}

extern "C" void kernel_launch(void* const* d_in, const int* in_sizes, int n_in,
                              void* d_out, int out_size) {
    const int*   entity = (const int*)  d_in[0];
    const int*   cl     = (const int*)  d_in[1];
    const int*   cr     = (const int*)  d_in[2];
    const float* emb    = (const float*)d_in[3];
    const float* W_bil  = (const float*)d_in[4];
    const float* W_tail = (const float*)d_in[5];
    const float* W_head = (const float*)d_in[6];
    const float* gamma  = (const float*)d_in[7];
    const float* beta   = (const float*)d_in[8];
    float* out = (float*)d_out;

    int batch   = in_sizes[0] / 2;             // 1024
    int pad_idx = in_sizes[3] / EMBED - 1;     // 100000

    transpose_w<<<(EMBED * EMBED + 255) / 256, 256>>>(W_tail, W_head);

    dim3 grid(batch);
    encoder_kernel<<<grid, NTHREADS>>>(entity, cl, cr, emb, W_bil,
                                       gamma, beta, out, batch, pad_idx);
}

// round 16
// speedup vs baseline: 1.0919x; 1.0919x over previous
#include <cuda_runtime.h>

#define EMBED     128
#define MAXN      200
#define NTHREADS  256
#define LN_EPS    1e-5f

// Interleaved pre-transposed weights: g_Wp[e*128+d] = (W_tail[d][e], W_head[d][e])
__device__ float2 g_Wp[EMBED * EMBED];

__global__ void transpose_w(const float* __restrict__ Wt, const float* __restrict__ Wh) {
    int i = blockIdx.x * blockDim.x + threadIdx.x;
    if (i < EMBED * EMBED) {
        int d = i >> 7;
        int e = i & 127;
        g_Wp[e * EMBED + d] = make_float2(Wt[i], Wh[i]);
    }
}

// One CTA = one batch element, BOTH sides. Score+exp+aggregate fused, 4 rows/iter,
// with MANUAL software pipelining: next iteration's rel-row loads are issued into
// the just-freed v registers before the current reduce chain, hiding their latency.
__global__ __launch_bounds__(NTHREADS, 4)
void encoder_kernel(const int*   __restrict__ entity,
                    const int*   __restrict__ conn_left,
                    const int*   __restrict__ conn_right,
                    const float* __restrict__ emb,
                    const float* __restrict__ W_bil,
                    const float* __restrict__ gamma,
                    const float* __restrict__ beta,
                    float*       __restrict__ out,
                    int batch, int pad_idx)
{
    const int b    = blockIdx.x;
    const int tid  = threadIdx.x;
    const int lane = tid & 31;
    const int wid  = tid >> 5;

    __shared__ float s_weak[EMBED];
    __shared__ float s_head[2][EMBED];
    __shared__ float s_qp[2 * EMBED];
    __shared__ __align__(16) unsigned s_roff[2][MAXN];   // rel row byte-offsets
    __shared__ __align__(16) unsigned s_toff[2][MAXN];   // tail row byte-offsets
    __shared__ float s_aggp[8][EMBED];
    __shared__ float s_agg[2][EMBED];
    __shared__ float s_part[2][2][EMBED];
    __shared__ float s_red[8];
    __shared__ float s_red2[8];

    // ---- Stage 0: heads, weak_rel, neighbor offsets for both sides ----
    if (tid < EMBED) {
        int e0 = entity[2 * b];
        int e1 = entity[2 * b + 1];
        float hl = __ldcs(&emb[(size_t)e0 * EMBED + tid]);
        float hr = __ldcs(&emb[(size_t)e1 * EMBED + tid]);
        s_weak[tid]    = hr - hl;
        s_head[0][tid] = hl;
        s_head[1][tid] = hr;
    }
    for (int i = tid; i < 2 * MAXN; i += NTHREADS) {
        int s = (i < MAXN) ? 0 : 1;
        int m = (i < MAXN) ? i : i - MAXN;
        const int* conn = (s == 0 ? conn_left : conn_right) + (long)b * MAXN * 2;
        int2 c = reinterpret_cast<const int2*>(conn)[m];
        s_roff[s][m] = (unsigned)c.x << 9;     // row * 512 bytes
        s_toff[s][m] = (unsigned)c.y << 9;
    }
    __syncthreads();

    // ---- Stage 1: q = weak_rel @ W_bil (shared by both sides), split-K ----
    {
        int half = tid >> 7;
        int e    = tid & 127;
        int d0   = half * 64;
        float acc = 0.f;
        #pragma unroll 8
        for (int d = d0; d < d0 + 64; d++)
            acc = fmaf(s_weak[d], W_bil[d * EMBED + e], acc);
        s_qp[half * EMBED + e] = acc;
    }
    __syncthreads();

    // ---- Stage 2 (FUSED + PIPELINED): score -> exp -> aggregate ----
    {
        float4 q0 = reinterpret_cast<const float4*>(s_qp)[lane];
        float4 q1 = reinterpret_cast<const float4*>(s_qp + EMBED)[lane];
        float4 qv = make_float4(q0.x + q1.x, q0.y + q1.y, q0.z + q1.z, q0.w + q1.w);

        const char* embB = reinterpret_cast<const char*>(emb) + (unsigned)(lane << 4);
        const unsigned pad_off = (unsigned)pad_idx << 9;

        const int s    = wid >> 2;
        const int w4   = wid & 3;
        const bool hi16 = (lane & 16) != 0;
        const bool hi8  = (lane & 8)  != 0;

        float  lsum = 0.f;
        float4 a01 = make_float4(0.f, 0.f, 0.f, 0.f);
        float4 a23 = make_float4(0.f, 0.f, 0.f, 0.f);

        // pipeline state: current rel offsets + in-flight rel rows
        uint4  ro;
        float4 v0, v1, v2, v3;

        // prologue: load iteration 0's rel rows
        {
            int4 r = *reinterpret_cast<const int4*>(&s_roff[s][w4 * 4]);
            ro = make_uint4((unsigned)r.x, (unsigned)r.y, (unsigned)r.z, (unsigned)r.w);
            v0 = __ldcs(reinterpret_cast<const float4*>(embB + ro.x));
            v1 = __ldcs(reinterpret_cast<const float4*>(embB + ro.y));
            v2 = __ldcs(reinterpret_cast<const float4*>(embB + ro.z));
            v3 = __ldcs(reinterpret_cast<const float4*>(embB + ro.w));
        }

        #pragma unroll
        for (int it = 0; it < 12; it++) {
            const int m = w4 * 4 + it * 16;

            // tail-row loads for THIS iteration (covered by the reduce chain below)
            int4 to = *reinterpret_cast<const int4*>(&s_toff[s][m]);
            float4 u0 = __ldcs(reinterpret_cast<const float4*>(embB + (unsigned)to.x));
            float4 u1 = __ldcs(reinterpret_cast<const float4*>(embB + (unsigned)to.y));
            float4 u2 = __ldcs(reinterpret_cast<const float4*>(embB + (unsigned)to.z));
            float4 u3 = __ldcs(reinterpret_cast<const float4*>(embB + (unsigned)to.w));

            // pad-check offset for my lane group (from current ro, before overwrite)
            unsigned gA = hi8  ? ro.z : ro.x;
            unsigned gB = hi8  ? ro.w : ro.y;
            unsigned my_off = hi16 ? gB : gA;

            // consume v -> p (v registers die here)
            float p0 = v0.x*qv.x + v0.y*qv.y + v0.z*qv.z + v0.w*qv.w;
            float p1 = v1.x*qv.x + v1.y*qv.y + v1.z*qv.z + v1.w*qv.w;
            float p2 = v2.x*qv.x + v2.y*qv.y + v2.z*qv.z + v2.w*qv.w;
            float p3 = v3.x*qv.x + v3.y*qv.y + v3.z*qv.z + v3.w*qv.w;

            // PIPELINE: issue NEXT iteration's rel loads into the freed v regs,
            // so they fly during the reduce chain + FMAs below.
            if (it < 11) {
                int4 rn = *reinterpret_cast<const int4*>(&s_roff[s][m + 16]);
                ro = make_uint4((unsigned)rn.x, (unsigned)rn.y, (unsigned)rn.z, (unsigned)rn.w);
                v0 = __ldcs(reinterpret_cast<const float4*>(embB + ro.x));
                v1 = __ldcs(reinterpret_cast<const float4*>(embB + ro.y));
                v2 = __ldcs(reinterpret_cast<const float4*>(embB + ro.z));
                v3 = __ldcs(reinterpret_cast<const float4*>(embB + ro.w));
            }

            // 4-row reduce in 5 shfls
            float x01 = hi16 ? p1 : p0;
            float y01 = hi16 ? p0 : p1;
            x01 += __shfl_xor_sync(0xffffffffu, y01, 16);
            float x23 = hi16 ? p3 : p2;
            float y23 = hi16 ? p2 : p3;
            x23 += __shfl_xor_sync(0xffffffffu, y23, 16);
            float x = hi8 ? x23 : x01;
            float y = hi8 ? x01 : x23;
            x += __shfl_xor_sync(0xffffffffu, y, 8);
            x += __shfl_xor_sync(0xffffffffu, x, 4);
            x += __shfl_xor_sync(0xffffffffu, x, 2);
            x += __shfl_xor_sync(0xffffffffu, x, 1);
            // lane groups: [0-7]=row0, [8-15]=row2, [16-23]=row1, [24-31]=row3

            float e = (my_off == pad_off) ? 0.f : __expf(x);

            float att0 = __shfl_sync(0xffffffffu, e, 0);
            float att2 = __shfl_sync(0xffffffffu, e, 8);
            float att1 = __shfl_sync(0xffffffffu, e, 16);
            float att3 = __shfl_sync(0xffffffffu, e, 24);
            lsum += (att0 + att1) + (att2 + att3);

            a01.x = fmaf(att0, u0.x, fmaf(att1, u1.x, a01.x));
            a01.y = fmaf(att0, u0.y, fmaf(att1, u1.y, a01.y));
            a01.z = fmaf(att0, u0.z, fmaf(att1, u1.z, a01.z));
            a01.w = fmaf(att0, u0.w, fmaf(att1, u1.w, a01.w));
            a23.x = fmaf(att2, u2.x, fmaf(att3, u3.x, a23.x));
            a23.y = fmaf(att2, u2.y, fmaf(att3, u3.y, a23.y));
            a23.z = fmaf(att2, u2.z, fmaf(att3, u3.z, a23.z));
            a23.w = fmaf(att2, u2.w, fmaf(att3, u3.w, a23.w));
        }

        // rows 192..199: warps w4==0,1 take one more (unpipelined) 4-row group
        if (w4 < 2) {
            const int m = 192 + w4 * 4;
            int4 r = *reinterpret_cast<const int4*>(&s_roff[s][m]);
            int4 to = *reinterpret_cast<const int4*>(&s_toff[s][m]);
            float4 w0 = __ldcs(reinterpret_cast<const float4*>(embB + (unsigned)r.x));
            float4 w1 = __ldcs(reinterpret_cast<const float4*>(embB + (unsigned)r.y));
            float4 w2 = __ldcs(reinterpret_cast<const float4*>(embB + (unsigned)r.z));
            float4 w3 = __ldcs(reinterpret_cast<const float4*>(embB + (unsigned)r.w));
            float4 u0 = __ldcs(reinterpret_cast<const float4*>(embB + (unsigned)to.x));
            float4 u1 = __ldcs(reinterpret_cast<const float4*>(embB + (unsigned)to.y));
            float4 u2 = __ldcs(reinterpret_cast<const float4*>(embB + (unsigned)to.z));
            float4 u3 = __ldcs(reinterpret_cast<const float4*>(embB + (unsigned)to.w));

            unsigned gA = hi8  ? (unsigned)r.z : (unsigned)r.x;
            unsigned gB = hi8  ? (unsigned)r.w : (unsigned)r.y;
            unsigned my_off = hi16 ? gB : gA;

            float p0 = w0.x*qv.x + w0.y*qv.y + w0.z*qv.z + w0.w*qv.w;
            float p1 = w1.x*qv.x + w1.y*qv.y + w1.z*qv.z + w1.w*qv.w;
            float p2 = w2.x*qv.x + w2.y*qv.y + w2.z*qv.z + w2.w*qv.w;
            float p3 = w3.x*qv.x + w3.y*qv.y + w3.z*qv.z + w3.w*qv.w;

            float x01 = hi16 ? p1 : p0;
            float y01 = hi16 ? p0 : p1;
            x01 += __shfl_xor_sync(0xffffffffu, y01, 16);
            float x23 = hi16 ? p3 : p2;
            float y23 = hi16 ? p2 : p3;
            x23 += __shfl_xor_sync(0xffffffffu, y23, 16);
            float x = hi8 ? x23 : x01;
            float y = hi8 ? x01 : x23;
            x += __shfl_xor_sync(0xffffffffu, y, 8);
            x += __shfl_xor_sync(0xffffffffu, x, 4);
            x += __shfl_xor_sync(0xffffffffu, x, 2);
            x += __shfl_xor_sync(0xffffffffu, x, 1);

            float e = (my_off == pad_off) ? 0.f : __expf(x);

            float att0 = __shfl_sync(0xffffffffu, e, 0);
            float att2 = __shfl_sync(0xffffffffu, e, 8);
            float att1 = __shfl_sync(0xffffffffu, e, 16);
            float att3 = __shfl_sync(0xffffffffu, e, 24);
            lsum += (att0 + att1) + (att2 + att3);

            a01.x = fmaf(att0, u0.x, fmaf(att1, u1.x, a01.x));
            a01.y = fmaf(att0, u0.y, fmaf(att1, u1.y, a01.y));
            a01.z = fmaf(att0, u0.z, fmaf(att1, u1.z, a01.z));
            a01.w = fmaf(att0, u0.w, fmaf(att1, u1.w, a01.w));
            a23.x = fmaf(att2, u2.x, fmaf(att3, u3.x, a23.x));
            a23.y = fmaf(att2, u2.y, fmaf(att3, u3.y, a23.y));
            a23.z = fmaf(att2, u2.z, fmaf(att3, u3.z, a23.z));
            a23.w = fmaf(att2, u2.w, fmaf(att3, u3.w, a23.w));
        }

        float4 at = make_float4(a01.x + a23.x, a01.y + a23.y,
                                a01.z + a23.z, a01.w + a23.w);
        reinterpret_cast<float4*>(s_aggp[wid])[lane] = at;
        if (lane == 0) s_red[wid] = lsum;
    }
    __syncthreads();

    // ---- Stage 3: reduce warp partials per side, normalize ----
    {
        int s = tid >> 7;
        int d = tid & 127;
        float tot = s_red[s * 4] + s_red[s * 4 + 1] + s_red[s * 4 + 2] + s_red[s * 4 + 3];
        float inv_sum = 1.f / tot;
        float a = s_aggp[s * 4][d] + s_aggp[s * 4 + 1][d]
                + s_aggp[s * 4 + 2][d] + s_aggp[s * 4 + 3][d];
        s_agg[s][d] = a * inv_sum;
    }
    __syncthreads();

    // ---- Stage 4: both matvecs share interleaved W loads (LDG.64, L1-cached) ----
    {
        int half = tid >> 7;
        int d    = tid & 127;
        int e0   = half * 64;
        float accL = 0.f, accR = 0.f;
        #pragma unroll 4
        for (int e = e0; e < e0 + 64; e++) {
            float2 w = g_Wp[e * EMBED + d];        // (wt, wh)
            accL = fmaf(s_agg[0][e],  w.x, accL);
            accL = fmaf(s_head[0][e], w.y, accL);
            accR = fmaf(s_agg[1][e],  w.x, accR);
            accR = fmaf(s_head[1][e], w.y, accR);
        }
        s_part[half][0][d] = accL;
        s_part[half][1][d] = accR;
    }
    __syncthreads();

    // ---- Stage 5: residual + LayerNorm per side ----
    {
        int s = tid >> 7;
        int d = tid & 127;
        float h = fmaxf(s_part[0][s][d] + s_part[1][s][d], 0.f);
        float x = h + s_head[s][d];

        float sx = x, sxx = x * x;
        #pragma unroll
        for (int o = 16; o; o >>= 1) {
            sx  += __shfl_xor_sync(0xffffffffu, sx,  o);
            sxx += __shfl_xor_sync(0xffffffffu, sxx, o);
        }
        if (lane == 0) { s_red[wid] = sx; s_red2[wid] = sxx; }
        __syncthreads();
        float tsum = s_red[s * 4]  + s_red[s * 4 + 1]  + s_red[s * 4 + 2]  + s_red[s * 4 + 3];
        float tsq  = s_red2[s * 4] + s_red2[s * 4 + 1] + s_red2[s * 4 + 2] + s_red2[s * 4 + 3];
        float mu      = tsum * (1.f / EMBED);
        float var     = tsq  * (1.f / EMBED) - mu * mu;
        float inv_std = rsqrtf(var + LN_EPS);
        float o = (x - mu) * inv_std * gamma[d] + beta[d];
        out[((long)s * batch + b) * EMBED + d] = o;
    }
}

extern "C" void kernel_launch(void* const* d_in, const int* in_sizes, int n_in,
                              void* d_out, int out_size) {
    const int*   entity = (const int*)  d_in[0];
    const int*   cl     = (const int*)  d_in[1];
    const int*   cr     = (const int*)  d_in[2];
    const float* emb    = (const float*)d_in[3];
    const float* W_bil  = (const float*)d_in[4];
    const float* W_tail = (const float*)d_in[5];
    const float* W_head = (const float*)d_in[6];
    const float* gamma  = (const float*)d_in[7];
    const float* beta   = (const float*)d_in[8];
    float* out = (float*)d_out;

    int batch   = in_sizes[0] / 2;             // 1024
    int pad_idx = in_sizes[3] / EMBED - 1;     // 100000

    transpose_w<<<(EMBED * EMBED + 255) / 256, 256>>>(W_tail, W_head);

    dim3 grid(batch);
    encoder_kernel<<<grid, NTHREADS>>>(entity, cl, cr, emb, W_bil,
                                       gamma, beta, out, batch, pad_idx);
}

// round 17
// speedup vs baseline: 1.1485x; 1.0519x over previous
#include <cuda_runtime.h>
#include <cuda_fp16.h>

#define EMBED     128
#define MAXN      200
#define NTHREADS  256
#define LN_EPS    1e-5f
#define N4        3200032          // (100001*128)/4 float4 groups

// Interleaved pre-transposed weights: g_Wp[e*128+d] = (W_tail[d][e], W_head[d][e])
__device__ float2 g_Wp[EMBED * EMBED];
// fp16 copy of the embedding table: row = 256 bytes, g_emb16[i] = 4 halves
__device__ uint2 g_emb16[N4];

__global__ void transpose_w(const float* __restrict__ Wt, const float* __restrict__ Wh) {
    int i = blockIdx.x * blockDim.x + threadIdx.x;
    if (i < EMBED * EMBED) {
        int d = i >> 7;
        int e = i & 127;
        g_Wp[e * EMBED + d] = make_float2(Wt[i], Wh[i]);
    }
}

// Convert the fp32 table to fp16 (runs every launch; table is L2-resident so ~7us)
__global__ __launch_bounds__(256)
void convert_emb(const float4* __restrict__ src, int n4) {
    int i = blockIdx.x * blockDim.x + threadIdx.x;
    if (i < n4) {
        float4 v = src[i];
        __half2 h0 = __floats2half2_rn(v.x, v.y);
        __half2 h1 = __floats2half2_rn(v.z, v.w);
        uint2 o;
        o.x = *reinterpret_cast<unsigned*>(&h0);
        o.y = *reinterpret_cast<unsigned*>(&h1);
        g_emb16[i] = o;
    }
}

// One CTA = one batch element, BOTH sides. Score+exp+aggregate fused, 4 rows/iter,
// manual software pipelining of rel-row loads. Neighbor gathers read the fp16
// table (half the L2 traffic); heads/weights/accumulation stay fp32.
__global__ __launch_bounds__(NTHREADS, 4)
void encoder_kernel(const int*   __restrict__ entity,
                    const int*   __restrict__ conn_left,
                    const int*   __restrict__ conn_right,
                    const float* __restrict__ emb,
                    const float* __restrict__ W_bil,
                    const float* __restrict__ gamma,
                    const float* __restrict__ beta,
                    float*       __restrict__ out,
                    int batch, int pad_idx)
{
    const int b    = blockIdx.x;
    const int tid  = threadIdx.x;
    const int lane = tid & 31;
    const int wid  = tid >> 5;

    __shared__ float s_weak[EMBED];
    __shared__ float s_head[2][EMBED];
    __shared__ float s_qp[2 * EMBED];
    __shared__ __align__(16) unsigned s_roff[2][MAXN];   // rel row byte-offsets (fp16 table)
    __shared__ __align__(16) unsigned s_toff[2][MAXN];   // tail row byte-offsets
    __shared__ float s_aggp[8][EMBED];
    __shared__ float s_agg[2][EMBED];
    __shared__ float s_part[2][2][EMBED];
    __shared__ float s_red[8];
    __shared__ float s_red2[8];

    // ---- Stage 0: heads (fp32 table), weak_rel, neighbor offsets ----
    if (tid < EMBED) {
        int e0 = entity[2 * b];
        int e1 = entity[2 * b + 1];
        float hl = __ldcs(&emb[(size_t)e0 * EMBED + tid]);
        float hr = __ldcs(&emb[(size_t)e1 * EMBED + tid]);
        s_weak[tid]    = hr - hl;
        s_head[0][tid] = hl;
        s_head[1][tid] = hr;
    }
    for (int i = tid; i < 2 * MAXN; i += NTHREADS) {
        int s = (i < MAXN) ? 0 : 1;
        int m = (i < MAXN) ? i : i - MAXN;
        const int* conn = (s == 0 ? conn_left : conn_right) + (long)b * MAXN * 2;
        int2 c = reinterpret_cast<const int2*>(conn)[m];
        s_roff[s][m] = (unsigned)c.x << 8;     // fp16 row = 256 bytes
        s_toff[s][m] = (unsigned)c.y << 8;
    }
    __syncthreads();

    // ---- Stage 1: q = weak_rel @ W_bil (shared by both sides), split-K ----
    {
        int half = tid >> 7;
        int e    = tid & 127;
        int d0   = half * 64;
        float acc = 0.f;
        #pragma unroll 8
        for (int d = d0; d < d0 + 64; d++)
            acc = fmaf(s_weak[d], W_bil[d * EMBED + e], acc);
        s_qp[half * EMBED + e] = acc;
    }
    __syncthreads();

    // ---- Stage 2 (FUSED + PIPELINED): score -> exp -> aggregate, fp16 gathers ----
    {
        float4 q0 = reinterpret_cast<const float4*>(s_qp)[lane];
        float4 q1 = reinterpret_cast<const float4*>(s_qp + EMBED)[lane];
        float4 qv = make_float4(q0.x + q1.x, q0.y + q1.y, q0.z + q1.z, q0.w + q1.w);

        const char* embB = reinterpret_cast<const char*>(g_emb16) + (unsigned)(lane << 3);
        const unsigned pad_off = (unsigned)pad_idx << 8;

        const int s    = wid >> 2;
        const int w4   = wid & 3;
        const bool hi16 = (lane & 16) != 0;
        const bool hi8  = (lane & 8)  != 0;

        float  lsum = 0.f;
        float4 a01 = make_float4(0.f, 0.f, 0.f, 0.f);
        float4 a23 = make_float4(0.f, 0.f, 0.f, 0.f);

        // half4 (uint2) -> float4
        auto h4f = [](uint2 r) {
            __half2 h0 = *reinterpret_cast<__half2*>(&r.x);
            __half2 h1 = *reinterpret_cast<__half2*>(&r.y);
            float2 f0 = __half22float2(h0);
            float2 f1 = __half22float2(h1);
            return make_float4(f0.x, f0.y, f1.x, f1.y);
        };

        // pipeline state: current rel offsets + in-flight rel rows
        uint4 ro;
        uint2 v0, v1, v2, v3;

        // prologue: load iteration 0's rel rows
        {
            int4 r = *reinterpret_cast<const int4*>(&s_roff[s][w4 * 4]);
            ro = make_uint4((unsigned)r.x, (unsigned)r.y, (unsigned)r.z, (unsigned)r.w);
            v0 = __ldcs(reinterpret_cast<const uint2*>(embB + ro.x));
            v1 = __ldcs(reinterpret_cast<const uint2*>(embB + ro.y));
            v2 = __ldcs(reinterpret_cast<const uint2*>(embB + ro.z));
            v3 = __ldcs(reinterpret_cast<const uint2*>(embB + ro.w));
        }

        #pragma unroll
        for (int it = 0; it < 12; it++) {
            const int m = w4 * 4 + it * 16;

            // tail-row loads for THIS iteration (covered by the reduce chain below)
            int4 to = *reinterpret_cast<const int4*>(&s_toff[s][m]);
            uint2 U0 = __ldcs(reinterpret_cast<const uint2*>(embB + (unsigned)to.x));
            uint2 U1 = __ldcs(reinterpret_cast<const uint2*>(embB + (unsigned)to.y));
            uint2 U2 = __ldcs(reinterpret_cast<const uint2*>(embB + (unsigned)to.z));
            uint2 U3 = __ldcs(reinterpret_cast<const uint2*>(embB + (unsigned)to.w));

            // pad-check offset for my lane group (from current ro, before overwrite)
            unsigned gA = hi8  ? ro.z : ro.x;
            unsigned gB = hi8  ? ro.w : ro.y;
            unsigned my_off = hi16 ? gB : gA;

            // consume v -> p (v registers die here)
            float4 vf0 = h4f(v0);
            float4 vf1 = h4f(v1);
            float4 vf2 = h4f(v2);
            float4 vf3 = h4f(v3);
            float p0 = vf0.x*qv.x + vf0.y*qv.y + vf0.z*qv.z + vf0.w*qv.w;
            float p1 = vf1.x*qv.x + vf1.y*qv.y + vf1.z*qv.z + vf1.w*qv.w;
            float p2 = vf2.x*qv.x + vf2.y*qv.y + vf2.z*qv.z + vf2.w*qv.w;
            float p3 = vf3.x*qv.x + vf3.y*qv.y + vf3.z*qv.z + vf3.w*qv.w;

            // PIPELINE: issue NEXT iteration's rel loads into the freed v regs
            if (it < 11) {
                int4 rn = *reinterpret_cast<const int4*>(&s_roff[s][m + 16]);
                ro = make_uint4((unsigned)rn.x, (unsigned)rn.y, (unsigned)rn.z, (unsigned)rn.w);
                v0 = __ldcs(reinterpret_cast<const uint2*>(embB + ro.x));
                v1 = __ldcs(reinterpret_cast<const uint2*>(embB + ro.y));
                v2 = __ldcs(reinterpret_cast<const uint2*>(embB + ro.z));
                v3 = __ldcs(reinterpret_cast<const uint2*>(embB + ro.w));
            }

            // 4-row reduce in 5 shfls
            float x01 = hi16 ? p1 : p0;
            float y01 = hi16 ? p0 : p1;
            x01 += __shfl_xor_sync(0xffffffffu, y01, 16);
            float x23 = hi16 ? p3 : p2;
            float y23 = hi16 ? p2 : p3;
            x23 += __shfl_xor_sync(0xffffffffu, y23, 16);
            float x = hi8 ? x23 : x01;
            float y = hi8 ? x01 : x23;
            x += __shfl_xor_sync(0xffffffffu, y, 8);
            x += __shfl_xor_sync(0xffffffffu, x, 4);
            x += __shfl_xor_sync(0xffffffffu, x, 2);
            x += __shfl_xor_sync(0xffffffffu, x, 1);
            // lane groups: [0-7]=row0, [8-15]=row2, [16-23]=row1, [24-31]=row3

            float e = (my_off == pad_off) ? 0.f : __expf(x);

            float att0 = __shfl_sync(0xffffffffu, e, 0);
            float att2 = __shfl_sync(0xffffffffu, e, 8);
            float att1 = __shfl_sync(0xffffffffu, e, 16);
            float att3 = __shfl_sync(0xffffffffu, e, 24);
            lsum += (att0 + att1) + (att2 + att3);

            float4 u0 = h4f(U0);
            float4 u1 = h4f(U1);
            float4 u2 = h4f(U2);
            float4 u3 = h4f(U3);
            a01.x = fmaf(att0, u0.x, fmaf(att1, u1.x, a01.x));
            a01.y = fmaf(att0, u0.y, fmaf(att1, u1.y, a01.y));
            a01.z = fmaf(att0, u0.z, fmaf(att1, u1.z, a01.z));
            a01.w = fmaf(att0, u0.w, fmaf(att1, u1.w, a01.w));
            a23.x = fmaf(att2, u2.x, fmaf(att3, u3.x, a23.x));
            a23.y = fmaf(att2, u2.y, fmaf(att3, u3.y, a23.y));
            a23.z = fmaf(att2, u2.z, fmaf(att3, u3.z, a23.z));
            a23.w = fmaf(att2, u2.w, fmaf(att3, u3.w, a23.w));
        }

        // rows 192..199: warps w4==0,1 take one more (unpipelined) 4-row group
        if (w4 < 2) {
            const int m = 192 + w4 * 4;
            int4 r  = *reinterpret_cast<const int4*>(&s_roff[s][m]);
            int4 to = *reinterpret_cast<const int4*>(&s_toff[s][m]);
            uint2 W0 = __ldcs(reinterpret_cast<const uint2*>(embB + (unsigned)r.x));
            uint2 W1 = __ldcs(reinterpret_cast<const uint2*>(embB + (unsigned)r.y));
            uint2 W2 = __ldcs(reinterpret_cast<const uint2*>(embB + (unsigned)r.z));
            uint2 W3 = __ldcs(reinterpret_cast<const uint2*>(embB + (unsigned)r.w));
            uint2 U0 = __ldcs(reinterpret_cast<const uint2*>(embB + (unsigned)to.x));
            uint2 U1 = __ldcs(reinterpret_cast<const uint2*>(embB + (unsigned)to.y));
            uint2 U2 = __ldcs(reinterpret_cast<const uint2*>(embB + (unsigned)to.z));
            uint2 U3 = __ldcs(reinterpret_cast<const uint2*>(embB + (unsigned)to.w));

            unsigned gA = hi8  ? (unsigned)r.z : (unsigned)r.x;
            unsigned gB = hi8  ? (unsigned)r.w : (unsigned)r.y;
            unsigned my_off = hi16 ? gB : gA;

            float4 wf0 = h4f(W0);
            float4 wf1 = h4f(W1);
            float4 wf2 = h4f(W2);
            float4 wf3 = h4f(W3);
            float p0 = wf0.x*qv.x + wf0.y*qv.y + wf0.z*qv.z + wf0.w*qv.w;
            float p1 = wf1.x*qv.x + wf1.y*qv.y + wf1.z*qv.z + wf1.w*qv.w;
            float p2 = wf2.x*qv.x + wf2.y*qv.y + wf2.z*qv.z + wf2.w*qv.w;
            float p3 = wf3.x*qv.x + wf3.y*qv.y + wf3.z*qv.z + wf3.w*qv.w;

            float x01 = hi16 ? p1 : p0;
            float y01 = hi16 ? p0 : p1;
            x01 += __shfl_xor_sync(0xffffffffu, y01, 16);
            float x23 = hi16 ? p3 : p2;
            float y23 = hi16 ? p2 : p3;
            x23 += __shfl_xor_sync(0xffffffffu, y23, 16);
            float x = hi8 ? x23 : x01;
            float y = hi8 ? x01 : x23;
            x += __shfl_xor_sync(0xffffffffu, y, 8);
            x += __shfl_xor_sync(0xffffffffu, x, 4);
            x += __shfl_xor_sync(0xffffffffu, x, 2);
            x += __shfl_xor_sync(0xffffffffu, x, 1);

            float e = (my_off == pad_off) ? 0.f : __expf(x);

            float att0 = __shfl_sync(0xffffffffu, e, 0);
            float att2 = __shfl_sync(0xffffffffu, e, 8);
            float att1 = __shfl_sync(0xffffffffu, e, 16);
            float att3 = __shfl_sync(0xffffffffu, e, 24);
            lsum += (att0 + att1) + (att2 + att3);

            float4 u0 = h4f(U0);
            float4 u1 = h4f(U1);
            float4 u2 = h4f(U2);
            float4 u3 = h4f(U3);
            a01.x = fmaf(att0, u0.x, fmaf(att1, u1.x, a01.x));
            a01.y = fmaf(att0, u0.y, fmaf(att1, u1.y, a01.y));
            a01.z = fmaf(att0, u0.z, fmaf(att1, u1.z, a01.z));
            a01.w = fmaf(att0, u0.w, fmaf(att1, u1.w, a01.w));
            a23.x = fmaf(att2, u2.x, fmaf(att3, u3.x, a23.x));
            a23.y = fmaf(att2, u2.y, fmaf(att3, u3.y, a23.y));
            a23.z = fmaf(att2, u2.z, fmaf(att3, u3.z, a23.z));
            a23.w = fmaf(att2, u2.w, fmaf(att3, u3.w, a23.w));
        }

        float4 at = make_float4(a01.x + a23.x, a01.y + a23.y,
                                a01.z + a23.z, a01.w + a23.w);
        reinterpret_cast<float4*>(s_aggp[wid])[lane] = at;
        if (lane == 0) s_red[wid] = lsum;
    }
    __syncthreads();

    // ---- Stage 3: reduce warp partials per side, normalize ----
    {
        int s = tid >> 7;
        int d = tid & 127;
        float tot = s_red[s * 4] + s_red[s * 4 + 1] + s_red[s * 4 + 2] + s_red[s * 4 + 3];
        float inv_sum = 1.f / tot;
        float a = s_aggp[s * 4][d] + s_aggp[s * 4 + 1][d]
                + s_aggp[s * 4 + 2][d] + s_aggp[s * 4 + 3][d];
        s_agg[s][d] = a * inv_sum;
    }
    __syncthreads();

    // ---- Stage 4: both matvecs share interleaved W loads (LDG.64, L1-cached) ----
    {
        int half = tid >> 7;
        int d    = tid & 127;
        int e0   = half * 64;
        float accL = 0.f, accR = 0.f;
        #pragma unroll 4
        for (int e = e0; e < e0 + 64; e++) {
            float2 w = g_Wp[e * EMBED + d];        // (wt, wh)
            accL = fmaf(s_agg[0][e],  w.x, accL);
            accL = fmaf(s_head[0][e], w.y, accL);
            accR = fmaf(s_agg[1][e],  w.x, accR);
            accR = fmaf(s_head[1][e], w.y, accR);
        }
        s_part[half][0][d] = accL;
        s_part[half][1][d] = accR;
    }
    __syncthreads();

    // ---- Stage 5: residual + LayerNorm per side ----
    {
        int s = tid >> 7;
        int d = tid & 127;
        float h = fmaxf(s_part[0][s][d] + s_part[1][s][d], 0.f);
        float x = h + s_head[s][d];

        float sx = x, sxx = x * x;
        #pragma unroll
        for (int o = 16; o; o >>= 1) {
            sx  += __shfl_xor_sync(0xffffffffu, sx,  o);
            sxx += __shfl_xor_sync(0xffffffffu, sxx, o);
        }
        if (lane == 0) { s_red[wid] = sx; s_red2[wid] = sxx; }
        __syncthreads();
        float tsum = s_red[s * 4]  + s_red[s * 4 + 1]  + s_red[s * 4 + 2]  + s_red[s * 4 + 3];
        float tsq  = s_red2[s * 4] + s_red2[s * 4 + 1] + s_red2[s * 4 + 2] + s_red2[s * 4 + 3];
        float mu      = tsum * (1.f / EMBED);
        float var     = tsq  * (1.f / EMBED) - mu * mu;
        float inv_std = rsqrtf(var + LN_EPS);
        float o = (x - mu) * inv_std * gamma[d] + beta[d];
        out[((long)s * batch + b) * EMBED + d] = o;
    }
}

extern "C" void kernel_launch(void* const* d_in, const int* in_sizes, int n_in,
                              void* d_out, int out_size) {
    const int*   entity = (const int*)  d_in[0];
    const int*   cl     = (const int*)  d_in[1];
    const int*   cr     = (const int*)  d_in[2];
    const float* emb    = (const float*)d_in[3];
    const float* W_bil  = (const float*)d_in[4];
    const float* W_tail = (const float*)d_in[5];
    const float* W_head = (const float*)d_in[6];
    const float* gamma  = (const float*)d_in[7];
    const float* beta   = (const float*)d_in[8];
    float* out = (float*)d_out;

    int batch   = in_sizes[0] / 2;             // 1024
    int pad_idx = in_sizes[3] / EMBED - 1;     // 100000
    int n4      = in_sizes[3] / 4;             // float4 groups in the table

    convert_emb<<<(n4 + 255) / 256, 256>>>(reinterpret_cast<const float4*>(emb), n4);
    transpose_w<<<(EMBED * EMBED + 255) / 256, 256>>>(W_tail, W_head);

    dim3 grid(batch);
    encoder_kernel<<<grid, NTHREADS>>>(entity, cl, cr, emb, W_bil,
                                       gamma, beta, out, batch, pad_idx);
}